// round 3
// baseline (speedup 1.0000x reference)
#include <cuda_runtime.h>
#include <math.h>

// Problem constants
constexpr int B_  = 2;
constexpr int L_  = 2048;
constexpr int H_  = 1024;
constexpr int NH_ = 16;
constexpr int HD_ = 64;   // head dim
constexpr int M_  = B_ * L_;  // 4096 rows for projections

// Scratch (device globals; no allocation allowed)
__device__ float g_qh[B_ * NH_ * L_ * HD_];  // [B,NH,L,HD]
__device__ float g_kh[B_ * NH_ * L_ * HD_];
__device__ float g_vh[B_ * NH_ * L_ * HD_];
__device__ float g_ao[B_ * L_ * H_];         // attention output, [B,L,H]

// ---------------------------------------------------------------------------
// 128x128 tiled fp32 GEMM core: out = A[4096,1024] @ W[1024,1024] + bias
// Double-buffered smem: loads for k-tile t+1 issue before compute on t.
// MODE 0: write out[m*H + n] (plain row-major)
// MODE 1: write head-split layout out[((b*NH + n/64)*L + l)*64 + n%64]
// 256 threads, 8x8 accum per thread, BK=16.
// ---------------------------------------------------------------------------
template <int MODE>
__device__ __forceinline__ void gemm128_body(const float* __restrict__ A,
                                             const float* __restrict__ W,
                                             const float* __restrict__ bias,
                                             float* __restrict__ out) {
    __shared__ float As[2][16][132];  // transposed, +4 pad kills store conflicts
    __shared__ float Bs[2][16][128];

    const int tid = threadIdx.x;
    const int tx  = tid & 15;   // 0..15 -> output cols
    const int ty  = tid >> 4;   // 0..15 -> output rows
    const int bn  = blockIdx.x; // N tile (0..7)
    const int bm  = blockIdx.y; // M tile (0..31)

    float acc[8][8];
#pragma unroll
    for (int i = 0; i < 8; i++)
#pragma unroll
        for (int j = 0; j < 8; j++) acc[i][j] = 0.0f;

    const float* Ab = A + (size_t)(bm * 128) * H_;
    const float* Wb = W + bn * 128;

    const int ar = tid >> 2;         // 0..63 : A tile row (then +64)
    const int ac = (tid & 3) * 4;    // 0,4,8,12 : A tile col (k)
    const int br = tid >> 5;         // 0..7  : B tile row (k) (then +8)
    const int bc = (tid & 31) * 4;   // 0..124 : B tile col

    // Prologue: load tile 0 into buffer 0
    {
#pragma unroll
        for (int rr = 0; rr < 128; rr += 64) {
            float4 a = *(const float4*)(Ab + (size_t)(ar + rr) * H_ + ac);
            As[0][ac + 0][ar + rr] = a.x;
            As[0][ac + 1][ar + rr] = a.y;
            As[0][ac + 2][ar + rr] = a.z;
            As[0][ac + 3][ar + rr] = a.w;
        }
#pragma unroll
        for (int rr = 0; rr < 16; rr += 8) {
            *(float4*)&Bs[0][br + rr][bc] =
                *(const float4*)(Wb + (size_t)(br + rr) * H_ + bc);
        }
    }
    __syncthreads();

    for (int k0 = 0; k0 < H_; k0 += 16) {
        const int buf = (k0 >> 4) & 1;
        const int nxt = buf ^ 1;

        // Issue loads for next tile first (hide gmem latency under compute)
        if (k0 + 16 < H_) {
            const int kn = k0 + 16;
#pragma unroll
            for (int rr = 0; rr < 128; rr += 64) {
                float4 a = *(const float4*)(Ab + (size_t)(ar + rr) * H_ + kn + ac);
                As[nxt][ac + 0][ar + rr] = a.x;
                As[nxt][ac + 1][ar + rr] = a.y;
                As[nxt][ac + 2][ar + rr] = a.z;
                As[nxt][ac + 3][ar + rr] = a.w;
            }
#pragma unroll
            for (int rr = 0; rr < 16; rr += 8) {
                *(float4*)&Bs[nxt][br + rr][bc] =
                    *(const float4*)(Wb + (size_t)(kn + br + rr) * H_ + bc);
            }
        }

        // Compute on current buffer
#pragma unroll
        for (int kk = 0; kk < 16; kk++) {
            float av[8], bv[8];
            *(float4*)&av[0] = *(const float4*)&As[buf][kk][ty * 8];
            *(float4*)&av[4] = *(const float4*)&As[buf][kk][ty * 8 + 4];
            *(float4*)&bv[0] = *(const float4*)&Bs[buf][kk][tx * 8];
            *(float4*)&bv[4] = *(const float4*)&Bs[buf][kk][tx * 8 + 4];
#pragma unroll
            for (int i = 0; i < 8; i++)
#pragma unroll
                for (int j = 0; j < 8; j++) acc[i][j] += av[i] * bv[j];
        }
        __syncthreads();
    }

    // Epilogue
    const int n0 = bn * 128 + tx * 8;
    float bvals[8];
#pragma unroll
    for (int j = 0; j < 8; j++) bvals[j] = bias[n0 + j];

#pragma unroll
    for (int i = 0; i < 8; i++) {
        const int m = bm * 128 + ty * 8 + i;
        if (MODE == 0) {
            float* op = out + (size_t)m * H_ + n0;
#pragma unroll
            for (int j = 0; j < 8; j += 4) {
                float4 v = make_float4(acc[i][j] + bvals[j],
                                       acc[i][j + 1] + bvals[j + 1],
                                       acc[i][j + 2] + bvals[j + 2],
                                       acc[i][j + 3] + bvals[j + 3]);
                *(float4*)(op + j) = v;
            }
        } else {
            // m = b*L + l ; n stays in one head since n0 % 8 == 0 and 8 <= 64
            const int b  = m >> 11;          // / L_
            const int l  = m & (L_ - 1);
            const int hh = n0 >> 6;
            const int d0 = n0 & 63;
            float* op = out + (((size_t)(b * NH_ + hh) * L_ + l) * HD_ + d0);
#pragma unroll
            for (int j = 0; j < 8; j += 4) {
                float4 v = make_float4(acc[i][j] + bvals[j],
                                       acc[i][j + 1] + bvals[j + 1],
                                       acc[i][j + 2] + bvals[j + 2],
                                       acc[i][j + 3] + bvals[j + 3]);
                *(float4*)(op + j) = v;
            }
        }
    }
}

// Fused Q/K/V projection: blockIdx.z selects which projection this CTA does.
__global__ __launch_bounds__(256) void gemm_qkv(
    const float* __restrict__ q, const float* __restrict__ k,
    const float* __restrict__ v,
    const float* __restrict__ Wq, const float* __restrict__ Wk,
    const float* __restrict__ Wv,
    const float* __restrict__ bq, const float* __restrict__ bk,
    const float* __restrict__ bv,
    float* __restrict__ oq, float* __restrict__ ok, float* __restrict__ ov) {
    const int z = blockIdx.z;
    const float* A    = (z == 0) ? q  : (z == 1) ? k  : v;
    const float* W    = (z == 0) ? Wq : (z == 1) ? Wk : Wv;
    const float* bias = (z == 0) ? bq : (z == 1) ? bk : bv;
    float* out        = (z == 0) ? oq : (z == 1) ? ok : ov;
    gemm128_body<1>(A, W, bias, out);
}

// Output projection
__global__ __launch_bounds__(256) void gemm_out(const float* __restrict__ A,
                                                const float* __restrict__ W,
                                                const float* __restrict__ bias,
                                                float* __restrict__ out) {
    gemm128_body<0>(A, W, bias, out);
}

// ---------------------------------------------------------------------------
// Flash-style attention. One CTA = 64 query rows of one (b,h).
// Streams 64-key tiles: S = Q K^T * 0.125 + mask, online softmax, O += P V.
// 256 threads: 16x16 grid, each thread owns S[4 rows][4 cols], O[4 rows][4 dims].
// Row reductions over the 16 threads of a row live in one half-warp -> shfl.
// ---------------------------------------------------------------------------
__global__ __launch_bounds__(256) void attn_kernel(const float* __restrict__ mask) {
    constexpr int LDT = 68;  // 64 + 4 pad
    extern __shared__ float sm[];
    float* Qs = sm;                // 64 x 68
    float* Ks = sm + 64 * LDT;     // 64 x 68
    float* Vs = sm + 2 * 64 * LDT; // 64 x 68
    float* Ps = sm + 3 * 64 * LDT; // 64 x 68

    const int tid = threadIdx.x;
    const int tx  = tid & 15;   // S cols / O dims
    const int ty  = tid >> 4;   // S rows
    const int qt  = blockIdx.x; // query tile (0..31)
    const int bh  = blockIdx.y; // b*NH + h (0..31)

    const float* qb     = g_qh + ((size_t)bh * L_ + qt * 64) * HD_;
    const float* kbase  = g_kh + (size_t)bh * L_ * HD_;
    const float* vbase  = g_vh + (size_t)bh * L_ * HD_;
    const float* mbase  = mask + ((size_t)bh * L_ + qt * 64) * L_;

    // Load Q tile
    for (int i = tid; i < 64 * 16; i += 256) {
        const int r = i >> 4, c4 = (i & 15) * 4;
        *(float4*)(Qs + r * LDT + c4) = *(const float4*)(qb + r * 64 + c4);
    }

    const int r0 = ty * 4;  // query rows owned
    const int c0 = tx * 4;  // key cols / output dims owned

    float mst[4], lst[4], Oa[4][4];
#pragma unroll
    for (int i = 0; i < 4; i++) {
        mst[i] = -INFINITY;
        lst[i] = 0.0f;
#pragma unroll
        for (int j = 0; j < 4; j++) Oa[i][j] = 0.0f;
    }

    for (int kb = 0; kb < L_ / 64; kb++) {
        __syncthreads();  // prior iter done reading Ks/Vs/Ps (and Q load done)
        const float* kp = kbase + kb * 64 * HD_;
        const float* vp = vbase + kb * 64 * HD_;
        for (int i = tid; i < 64 * 16; i += 256) {
            const int r = i >> 4, c4 = (i & 15) * 4;
            *(float4*)(Ks + r * LDT + c4) = *(const float4*)(kp + r * 64 + c4);
            *(float4*)(Vs + r * LDT + c4) = *(const float4*)(vp + r * 64 + c4);
        }
        __syncthreads();

        // S = Q K^T
        float acc[4][4];
#pragma unroll
        for (int i = 0; i < 4; i++)
#pragma unroll
            for (int j = 0; j < 4; j++) acc[i][j] = 0.0f;

#pragma unroll
        for (int kk = 0; kk < 64; kk += 4) {
            float qf[4][4], kf[4][4];
#pragma unroll
            for (int i = 0; i < 4; i++)
                *(float4*)qf[i] = *(const float4*)(Qs + (r0 + i) * LDT + kk);
#pragma unroll
            for (int j = 0; j < 4; j++)
                *(float4*)kf[j] = *(const float4*)(Ks + (c0 + j) * LDT + kk);
#pragma unroll
            for (int i = 0; i < 4; i++)
#pragma unroll
                for (int j = 0; j < 4; j++)
                    acc[i][j] += qf[i][0] * kf[j][0] + qf[i][1] * kf[j][1] +
                                 qf[i][2] * kf[j][2] + qf[i][3] * kf[j][3];
        }

        // scale + additive mask
#pragma unroll
        for (int i = 0; i < 4; i++) {
            float4 mv = *(const float4*)(mbase + (size_t)(r0 + i) * L_ + kb * 64 + c0);
            acc[i][0] = acc[i][0] * 0.125f + mv.x;
            acc[i][1] = acc[i][1] * 0.125f + mv.y;
            acc[i][2] = acc[i][2] * 0.125f + mv.z;
            acc[i][3] = acc[i][3] * 0.125f + mv.w;
        }

        // Online softmax (reduce across the 16 threads of each row = half warp)
#pragma unroll
        for (int i = 0; i < 4; i++) {
            float mx = fmaxf(fmaxf(acc[i][0], acc[i][1]), fmaxf(acc[i][2], acc[i][3]));
#pragma unroll
            for (int off = 8; off >= 1; off >>= 1)
                mx = fmaxf(mx, __shfl_xor_sync(0xffffffffu, mx, off));
            const float mn = fmaxf(mst[i], mx);
            const float al = __expf(mst[i] - mn);
            mst[i] = mn;
            float s = 0.0f;
#pragma unroll
            for (int j = 0; j < 4; j++) {
                const float p = __expf(acc[i][j] - mn);
                acc[i][j] = p;
                s += p;
            }
#pragma unroll
            for (int off = 8; off >= 1; off >>= 1)
                s += __shfl_xor_sync(0xffffffffu, s, off);
            lst[i] = lst[i] * al + s;
#pragma unroll
            for (int j = 0; j < 4; j++) Oa[i][j] *= al;
        }

        // Stage P through smem (safe: nobody reads Ps between loop-top sync and here)
#pragma unroll
        for (int i = 0; i < 4; i++)
            *(float4*)(Ps + (r0 + i) * LDT + c0) =
                make_float4(acc[i][0], acc[i][1], acc[i][2], acc[i][3]);
        __syncthreads();

        // O += P @ V
#pragma unroll
        for (int c = 0; c < 64; c += 4) {
            float pf[4][4], vf[4][4];
#pragma unroll
            for (int i = 0; i < 4; i++)
                *(float4*)pf[i] = *(const float4*)(Ps + (r0 + i) * LDT + c);
#pragma unroll
            for (int t = 0; t < 4; t++)
                *(float4*)vf[t] = *(const float4*)(Vs + (c + t) * LDT + c0);
#pragma unroll
            for (int i = 0; i < 4; i++)
#pragma unroll
                for (int j = 0; j < 4; j++)
                    Oa[i][j] += pf[i][0] * vf[0][j] + pf[i][1] * vf[1][j] +
                                pf[i][2] * vf[2][j] + pf[i][3] * vf[3][j];
        }
    }

    // Write merged-head output [B, L, H]
    const int b  = bh / NH_;
    const int hh = bh % NH_;
#pragma unroll
    for (int i = 0; i < 4; i++) {
        const float inv = 1.0f / lst[i];
        float* op = g_ao + ((size_t)b * L_ + qt * 64 + r0 + i) * H_ + hh * 64 + c0;
        *(float4*)op = make_float4(Oa[i][0] * inv, Oa[i][1] * inv,
                                   Oa[i][2] * inv, Oa[i][3] * inv);
    }
}

// ---------------------------------------------------------------------------
// Launch
// ---------------------------------------------------------------------------
extern "C" void kernel_launch(void* const* d_in, const int* in_sizes, int n_in,
                              void* d_out, int out_size) {
    const float* q    = (const float*)d_in[0];
    const float* k    = (const float*)d_in[1];
    const float* v    = (const float*)d_in[2];
    const float* mask = (const float*)d_in[3];
    const float* Wq   = (const float*)d_in[4];
    const float* bq   = (const float*)d_in[5];
    const float* Wk   = (const float*)d_in[6];
    const float* bk   = (const float*)d_in[7];
    const float* Wv   = (const float*)d_in[8];
    const float* bv   = (const float*)d_in[9];
    const float* Wo   = (const float*)d_in[10];
    const float* bo   = (const float*)d_in[11];
    float* out = (float*)d_out;

    float *pqh, *pkh, *pvh, *pao;
    cudaGetSymbolAddress((void**)&pqh, g_qh);
    cudaGetSymbolAddress((void**)&pkh, g_kh);
    cudaGetSymbolAddress((void**)&pvh, g_vh);
    cudaGetSymbolAddress((void**)&pao, g_ao);

    const size_t attn_smem = 4 * 64 * 68 * sizeof(float);  // 69632 B
    cudaFuncSetAttribute(attn_kernel, cudaFuncAttributeMaxDynamicSharedMemorySize,
                         (int)attn_smem);

    dim3 gqkv(H_ / 128, M_ / 128, 3);  // (8, 32, 3)
    gemm_qkv<<<gqkv, 256>>>(q, k, v, Wq, Wk, Wv, bq, bk, bv, pqh, pkh, pvh);

    attn_kernel<<<dim3(L_ / 64, B_ * NH_), 256, attn_smem>>>(mask);

    dim3 gp(H_ / 128, M_ / 128);  // (8, 32)
    gemm_out<<<gp, 256>>>(pao, Wo, bo, out);
}

// round 9
// speedup vs baseline: 2.6276x; 2.6276x over previous
#include <cuda_runtime.h>
#include <cuda_bf16.h>
#include <cstdint>
#include <math.h>

// Problem constants
constexpr int B_  = 2;
constexpr int L_  = 2048;
constexpr int H_  = 1024;
constexpr int NH_ = 16;
constexpr int HD_ = 64;
constexpr int M_  = B_ * L_;        // 4096
constexpr int NM_ = M_ * H_;        // 4M elems
constexpr int HH_ = H_ * H_;        // 1M elems

// fp32 head-split Q/K/V (kept for bisection fallback; also written by MODE 1)
__device__ float g_qh[NM_];
__device__ float g_kh[NM_];
__device__ float g_vh[NM_];

// bf16 split scratch
__device__ __nv_bfloat16 g_inh[3 * NM_];  // q,k,v inputs hi
__device__ __nv_bfloat16 g_inl[3 * NM_];  // lo
__device__ __nv_bfloat16 g_wth[4 * HH_];  // Wq,Wk,Wv,Wo TRANSPOSED [n][k] hi
__device__ __nv_bfloat16 g_wtl[4 * HH_];  // lo
// head-split bf16 hi/lo Q,K,V (projection outputs)
__device__ __nv_bfloat16 g_qsh[NM_], g_qsl[NM_];
__device__ __nv_bfloat16 g_ksh[NM_], g_ksl[NM_];
__device__ __nv_bfloat16 g_vsh[NM_], g_vsl[NM_];
// attention output hi/lo (merged [B,L,H])
__device__ __nv_bfloat16 g_aoh[NM_], g_aol[NM_];

// ---------------------------------------------------------------------------
// mma.sync helpers (base sm_103 target legal: no 'a'-suffix features)
// ---------------------------------------------------------------------------
__device__ __forceinline__ uint32_t smem_u32(const void* p) {
    uint32_t a;
    asm("{ .reg .u64 t; cvta.to.shared.u64 t, %1; cvt.u32.u64 %0, t; }" : "=r"(a) : "l"(p));
    return a;
}
__device__ __forceinline__ void ldmx4(uint32_t* r, uint32_t addr) {
    asm volatile("ldmatrix.sync.aligned.m8n8.x4.shared.b16 {%0,%1,%2,%3}, [%4];"
                 : "=r"(r[0]), "=r"(r[1]), "=r"(r[2]), "=r"(r[3]) : "r"(addr));
}
__device__ __forceinline__ void ldmx2(uint32_t* r, uint32_t addr) {
    asm volatile("ldmatrix.sync.aligned.m8n8.x2.shared.b16 {%0,%1}, [%2];"
                 : "=r"(r[0]), "=r"(r[1]) : "r"(addr));
}
__device__ __forceinline__ void ldmx2t(uint32_t* r, uint32_t addr) {
    asm volatile("ldmatrix.sync.aligned.m8n8.x2.trans.shared.b16 {%0,%1}, [%2];"
                 : "=r"(r[0]), "=r"(r[1]) : "r"(addr));
}
__device__ __forceinline__ void mma_bf16(float* d, const uint32_t* a, const uint32_t* b) {
    asm volatile(
        "mma.sync.aligned.m16n8k16.row.col.f32.bf16.bf16.f32 "
        "{%0,%1,%2,%3}, {%4,%5,%6,%7}, {%8,%9}, {%0,%1,%2,%3};"
        : "+f"(d[0]), "+f"(d[1]), "+f"(d[2]), "+f"(d[3])
        : "r"(a[0]), "r"(a[1]), "r"(a[2]), "r"(a[3]), "r"(b[0]), "r"(b[1]));
}
// split two fp32 into packed bf16 hi + residual lo
__device__ __forceinline__ void split2(float a, float b, uint32_t& hi, uint32_t& lo) {
    __nv_bfloat16 ha = __float2bfloat16(a), hb = __float2bfloat16(b);
    __nv_bfloat162 H(ha, hb);
    __nv_bfloat162 Lo(__float2bfloat16(a - __bfloat162float(ha)),
                      __float2bfloat16(b - __bfloat162float(hb)));
    hi = *(uint32_t*)&H;
    lo = *(uint32_t*)&Lo;
}

// ---------------------------------------------------------------------------
// Split kernels: fp32 -> (hi, lo) bf16
// ---------------------------------------------------------------------------
__global__ __launch_bounds__(256) void split3_kernel(const float* __restrict__ a0,
                                                     const float* __restrict__ a1,
                                                     const float* __restrict__ a2) {
    const int z = blockIdx.y;
    const float* src = (z == 0) ? a0 : (z == 1) ? a1 : a2;
    __nv_bfloat16* hi = g_inh + (size_t)z * NM_;
    __nv_bfloat16* lo = g_inl + (size_t)z * NM_;
    const int i = (blockIdx.x * 256 + threadIdx.x) * 4;
    if (i < NM_) {
        float4 v = *(const float4*)(src + i);
        uint32_t h0, l0, h1, l1;
        split2(v.x, v.y, h0, l0);
        split2(v.z, v.w, h1, l1);
        *(uint32_t*)(hi + i)     = h0;
        *(uint32_t*)(hi + i + 2) = h1;
        *(uint32_t*)(lo + i)     = l0;
        *(uint32_t*)(lo + i + 2) = l1;
    }
}

// Transpose + split weights: Wt[n][k] = split(W[k][n]). 32x32 smem tiles.
__global__ __launch_bounds__(256) void wsplit_t_kernel(const float* __restrict__ w0,
                                                       const float* __restrict__ w1,
                                                       const float* __restrict__ w2,
                                                       const float* __restrict__ w3) {
    __shared__ float t[32][33];
    const int z = blockIdx.z;
    const float* W = (z == 0) ? w0 : (z == 1) ? w1 : (z == 2) ? w2 : w3;
    __nv_bfloat16* th = g_wth + (size_t)z * HH_;
    __nv_bfloat16* tl = g_wtl + (size_t)z * HH_;
    const int tx = threadIdx.x & 31, ty = threadIdx.x >> 5;  // 32x8
    const int n0 = blockIdx.x * 32, k0 = blockIdx.y * 32;
#pragma unroll
    for (int r = 0; r < 4; r++)
        t[ty + r * 8][tx] = W[(size_t)(k0 + ty + r * 8) * H_ + n0 + tx];
    __syncthreads();
#pragma unroll
    for (int r = 0; r < 4; r++) {
        const int n = n0 + ty + r * 8;
        const float v = t[tx][ty + r * 8];
        __nv_bfloat16 h = __float2bfloat16(v);
        th[(size_t)n * H_ + k0 + tx] = h;
        tl[(size_t)n * H_ + k0 + tx] = __float2bfloat16(v - __bfloat162float(h));
    }
}

// ---------------------------------------------------------------------------
// mma.sync split-bf16 GEMM: out[4096,1024] = A @ W + bias.
// CTA 128x128, BK=32, double-buffered smem. 8 warps (2m x 4n), warp 64x32.
// D = Ah*Bh + Ah*Bl + Al*Bh (fp32 accum). B given TRANSPOSED [n][k].
// MODE 0: fp32 row-major out.
// MODE 1: head-split; writes fp32 AND bf16 hi/lo.
// ---------------------------------------------------------------------------
constexpr int GBM = 128, GBN = 128, GBK = 32;
constexpr int NKC = H_ / GBK;                 // 32 k-chunks
constexpr int TPAD = 40;                      // padded row, bf16 elems (80B)
constexpr int TILE_B = 128 * TPAD * 2;        // 10240 bytes per tile
constexpr int BUF_B = 4 * TILE_B;             // Ah,Al,Bh,Bl = 40960
constexpr int GSMEM = 2 * BUF_B;              // 81920

template <int MODE>
__device__ __forceinline__ void gemm_mma_body(const __nv_bfloat16* __restrict__ Ah,
                                              const __nv_bfloat16* __restrict__ Al,
                                              const __nv_bfloat16* __restrict__ Bh,
                                              const __nv_bfloat16* __restrict__ Bl,
                                              const float* __restrict__ bias,
                                              float* __restrict__ out,
                                              __nv_bfloat16* __restrict__ outh,
                                              __nv_bfloat16* __restrict__ outl) {
    extern __shared__ __align__(16) char smem[];
    const int tid = threadIdx.x, lane = tid & 31, wid = tid >> 5;
    const int bn = blockIdx.x, bm = blockIdx.y;
    const int wm = (wid & 1) * 64;
    const int wn = (wid >> 1) * 32;

    const __nv_bfloat16* gAh = Ah + (size_t)(bm * GBM) * H_;
    const __nv_bfloat16* gAl = Al + (size_t)(bm * GBM) * H_;
    const __nv_bfloat16* gBh = Bh + (size_t)(bn * GBN) * H_;
    const __nv_bfloat16* gBl = Bl + (size_t)(bn * GBN) * H_;

    float acc[4][4][4];
#pragma unroll
    for (int a = 0; a < 4; a++)
#pragma unroll
        for (int b = 0; b < 4; b++)
#pragma unroll
            for (int c = 0; c < 4; c++) acc[a][b][c] = 0.0f;

    auto load_chunk = [&](int kc, int buf) {
        char* sb = smem + buf * BUF_B;
        const int col = kc * GBK;
#pragma unroll
        for (int ii = 0; ii < 2; ii++) {
            const int i = tid + ii * 256;
            const int r = i >> 2, c16 = i & 3;
            const int off = r * (TPAD * 2) + c16 * 16;
            const size_t go = (size_t)r * H_ + col + c16 * 8;
            *(uint4*)(sb + off)              = *(const uint4*)(gAh + go);
            *(uint4*)(sb + TILE_B + off)     = *(const uint4*)(gAl + go);
            *(uint4*)(sb + 2 * TILE_B + off) = *(const uint4*)(gBh + go);
            *(uint4*)(sb + 3 * TILE_B + off) = *(const uint4*)(gBl + go);
        }
    };

    const uint32_t smb = smem_u32(smem);
    load_chunk(0, 0);
    __syncthreads();

    for (int kc = 0; kc < NKC; kc++) {
        const int buf = kc & 1;
        if (kc + 1 < NKC) load_chunk(kc + 1, buf ^ 1);

        const uint32_t sb = smb + buf * BUF_B;
#pragma unroll
        for (int ks = 0; ks < 2; ks++) {
            uint32_t afh[4][4], afl[4][4];
            {
                const int rA = wm + (lane & 15);
                const int cA = ks * 16 + ((lane & 16) ? 8 : 0);
#pragma unroll
                for (int mt = 0; mt < 4; mt++) {
                    const uint32_t ad = sb + (rA + mt * 16) * (TPAD * 2) + cA * 2;
                    ldmx4(afh[mt], ad);
                    ldmx4(afl[mt], ad + TILE_B);
                }
            }
            uint32_t bfh[4][2], bfl[4][2];
            {
                const int rB = wn + (lane & 7);
                const int cB = ks * 16 + (lane & 8);
#pragma unroll
                for (int nt = 0; nt < 4; nt++) {
                    const uint32_t bd = sb + 2 * TILE_B + (rB + nt * 8) * (TPAD * 2) + cB * 2;
                    ldmx2(bfh[nt], bd);
                    ldmx2(bfl[nt], bd + TILE_B);
                }
            }
#pragma unroll
            for (int mt = 0; mt < 4; mt++)
#pragma unroll
                for (int nt = 0; nt < 4; nt++) {
                    mma_bf16(acc[mt][nt], afh[mt], bfh[nt]);
                    mma_bf16(acc[mt][nt], afh[mt], bfl[nt]);
                    mma_bf16(acc[mt][nt], afl[mt], bfh[nt]);
                }
        }
        __syncthreads();
    }

    const int lr = lane >> 2, lc = (lane & 3) * 2;
#pragma unroll
    for (int mt = 0; mt < 4; mt++) {
#pragma unroll
        for (int nt = 0; nt < 4; nt++) {
            const int c = bn * GBN + wn + nt * 8 + lc;
            const float b0 = bias[c], b1 = bias[c + 1];
#pragma unroll
            for (int h = 0; h < 2; h++) {
                const int row = bm * GBM + wm + mt * 16 + lr + h * 8;
                const float v0 = acc[mt][nt][h * 2 + 0] + b0;
                const float v1 = acc[mt][nt][h * 2 + 1] + b1;
                if (MODE == 0) {
                    *(float2*)(out + (size_t)row * H_ + c) = make_float2(v0, v1);
                } else {
                    const int bb = row >> 11, l = row & (L_ - 1);
                    const int hh = c >> 6, d0 = c & 63;
                    const size_t idx = ((size_t)(bb * NH_ + hh) * L_ + l) * HD_ + d0;
                    *(float2*)(out + idx) = make_float2(v0, v1);
                    uint32_t ph, pl;
                    split2(v0, v1, ph, pl);
                    *(uint32_t*)(outh + idx) = ph;
                    *(uint32_t*)(outl + idx) = pl;
                }
            }
        }
    }
}

__global__ __launch_bounds__(256) void gemm_qkv_tc(const float* __restrict__ bq,
                                                   const float* __restrict__ bk,
                                                   const float* __restrict__ bv) {
    const int z = blockIdx.z;
    const float* bias = (z == 0) ? bq : (z == 1) ? bk : bv;
    float* outf = (z == 0) ? g_qh : (z == 1) ? g_kh : g_vh;
    __nv_bfloat16* oh = (z == 0) ? g_qsh : (z == 1) ? g_ksh : g_vsh;
    __nv_bfloat16* ol = (z == 0) ? g_qsl : (z == 1) ? g_ksl : g_vsl;
    gemm_mma_body<1>(g_inh + (size_t)z * NM_, g_inl + (size_t)z * NM_,
                     g_wth + (size_t)z * HH_, g_wtl + (size_t)z * HH_, bias,
                     outf, oh, ol);
}

__global__ __launch_bounds__(256) void gemm_out_tc(const float* __restrict__ bo,
                                                   float* __restrict__ out) {
    gemm_mma_body<0>(g_aoh, g_aol, g_wth + (size_t)3 * HH_, g_wtl + (size_t)3 * HH_,
                     bo, out, nullptr, nullptr);
}

// ---------------------------------------------------------------------------
// mma.sync flash attention. CTA = 128 queries of one (b,h); 8 warps x 16 rows.
// Key tiles of 64. S = Qh*Kh + Qh*Kl + Ql*Kh; softmax fp32 in regs;
// O += Ph*Vh + Ph*Vl + Pl*Vh. P stays in registers (S D-frag == PV A-frag).
// ---------------------------------------------------------------------------
constexpr int AQ = 128, AKT = 64;
constexpr int AROW = 72 * 2;          // 144B padded row
constexpr int A_QL = 128 * AROW / 2 * 0 + 18432;  // Q lo at 18432
constexpr int A_KH = 0, A_KL = 9216, A_VH = 18432, A_VL = 27648;
constexpr int ASMEM = 36864;

__global__ __launch_bounds__(256, 1) void attn_mma(const float* __restrict__ mask) {
    extern __shared__ __align__(16) char sm[];
    const uint32_t smb = smem_u32(sm);
    const int tid = threadIdx.x, lane = tid & 31, w = tid >> 5;
    const int qt = blockIdx.x;            // 0..15
    const int bh = blockIdx.y;            // 0..31

    // Stage Q tile (128 x 64) hi/lo
    {
        const __nv_bfloat16* qh = g_qsh + ((size_t)bh * L_ + qt * AQ) * HD_;
        const __nv_bfloat16* ql = g_qsl + ((size_t)bh * L_ + qt * AQ) * HD_;
        for (int i = tid; i < 128 * 8; i += 256) {
            const int r = i >> 3, c = i & 7;
            *(uint4*)(sm + r * AROW + c * 16)         = *(const uint4*)(qh + (size_t)r * HD_ + c * 8);
            *(uint4*)(sm + A_QL + r * AROW + c * 16)  = *(const uint4*)(ql + (size_t)r * HD_ + c * 8);
        }
    }
    __syncthreads();

    // Q fragments to registers (4 k-steps, hi/lo)
    uint32_t qfh[4][4], qfl[4][4];
    {
        const int rq = w * 16 + (lane & 15);
#pragma unroll
        for (int ks = 0; ks < 4; ks++) {
            const uint32_t ad = smb + rq * AROW + (ks * 16 + ((lane & 16) ? 8 : 0)) * 2;
            ldmx4(qfh[ks], ad);
            ldmx4(qfl[ks], ad + A_QL);
        }
    }
    __syncthreads();  // Q staging consumed; smem reusable for K/V

    float accO[8][4];
#pragma unroll
    for (int nt = 0; nt < 8; nt++)
#pragma unroll
        for (int c = 0; c < 4; c++) accO[nt][c] = 0.0f;
    float mrow[2] = {-INFINITY, -INFINITY};
    float lrow[2] = {0.0f, 0.0f};

    const __nv_bfloat16* kbh = g_ksh + (size_t)bh * L_ * HD_;
    const __nv_bfloat16* kbl = g_ksl + (size_t)bh * L_ * HD_;
    const __nv_bfloat16* vbh = g_vsh + (size_t)bh * L_ * HD_;
    const __nv_bfloat16* vbl = g_vsl + (size_t)bh * L_ * HD_;
    const float* mb = mask + ((size_t)bh * L_ + qt * AQ) * L_;
    const int lr = lane >> 2, lc = (lane & 3) * 2;

    for (int kt = 0; kt < L_ / AKT; kt++) {
        __syncthreads();
        // Load K/V tiles (64 x 64) hi/lo
        for (int i = tid; i < 64 * 8; i += 256) {
            const int r = i >> 3, c = i & 7;
            const size_t go = (size_t)(kt * AKT + r) * HD_ + c * 8;
            const int off = r * AROW + c * 16;
            *(uint4*)(sm + A_KH + off) = *(const uint4*)(kbh + go);
            *(uint4*)(sm + A_KL + off) = *(const uint4*)(kbl + go);
            *(uint4*)(sm + A_VH + off) = *(const uint4*)(vbh + go);
            *(uint4*)(sm + A_VL + off) = *(const uint4*)(vbl + go);
        }
        // Prefetch mask values for this thread's S elements
        float2 mk[2][8];
#pragma unroll
        for (int h = 0; h < 2; h++) {
            const size_t mrowbase = (size_t)(w * 16 + lr + h * 8) * L_ + kt * AKT;
#pragma unroll
            for (int nt = 0; nt < 8; nt++)
                mk[h][nt] = *(const float2*)(mb + mrowbase + nt * 8 + lc);
        }
        __syncthreads();

        // S = Q K^T (split 3-term)
        float s[8][4];
#pragma unroll
        for (int nt = 0; nt < 8; nt++)
#pragma unroll
            for (int c = 0; c < 4; c++) s[nt][c] = 0.0f;
#pragma unroll
        for (int nt = 0; nt < 8; nt++) {
#pragma unroll
            for (int ks = 0; ks < 4; ks++) {
                uint32_t kh[2], kl[2];
                const uint32_t ad = smb + A_KH + (nt * 8 + (lane & 7)) * AROW +
                                    (ks * 16 + (lane & 8)) * 2;
                ldmx2(kh, ad);
                ldmx2(kl, ad + (A_KL - A_KH));
                mma_bf16(s[nt], qfh[ks], kh);
                mma_bf16(s[nt], qfh[ks], kl);
                mma_bf16(s[nt], qfl[ks], kh);
            }
        }

        // scale + mask + online softmax
        float tmax[2] = {-INFINITY, -INFINITY};
#pragma unroll
        for (int nt = 0; nt < 8; nt++) {
#pragma unroll
            for (int h = 0; h < 2; h++) {
                float x0 = s[nt][h * 2 + 0] * 0.125f + mk[h][nt].x;
                float x1 = s[nt][h * 2 + 1] * 0.125f + mk[h][nt].y;
                s[nt][h * 2 + 0] = x0;
                s[nt][h * 2 + 1] = x1;
                tmax[h] = fmaxf(tmax[h], fmaxf(x0, x1));
            }
        }
#pragma unroll
        for (int h = 0; h < 2; h++) {
            tmax[h] = fmaxf(tmax[h], __shfl_xor_sync(0xffffffffu, tmax[h], 1));
            tmax[h] = fmaxf(tmax[h], __shfl_xor_sync(0xffffffffu, tmax[h], 2));
        }
        float alpha[2], rsum[2] = {0.0f, 0.0f};
#pragma unroll
        for (int h = 0; h < 2; h++) {
            const float mn = fmaxf(mrow[h], tmax[h]);
            alpha[h] = __expf(mrow[h] - mn);
            mrow[h] = mn;
        }
#pragma unroll
        for (int nt = 0; nt < 8; nt++) {
#pragma unroll
            for (int h = 0; h < 2; h++) {
                const float p0 = __expf(s[nt][h * 2 + 0] - mrow[h]);
                const float p1 = __expf(s[nt][h * 2 + 1] - mrow[h]);
                s[nt][h * 2 + 0] = p0;
                s[nt][h * 2 + 1] = p1;
                rsum[h] += p0 + p1;
            }
        }
#pragma unroll
        for (int h = 0; h < 2; h++) {
            rsum[h] += __shfl_xor_sync(0xffffffffu, rsum[h], 1);
            rsum[h] += __shfl_xor_sync(0xffffffffu, rsum[h], 2);
            lrow[h] = lrow[h] * alpha[h] + rsum[h];
        }
#pragma unroll
        for (int nt = 0; nt < 8; nt++) {
            accO[nt][0] *= alpha[0];
            accO[nt][1] *= alpha[0];
            accO[nt][2] *= alpha[1];
            accO[nt][3] *= alpha[1];
        }

        // O += P V (split 3-term); P D-frags map directly to A-frags
#pragma unroll
        for (int ks = 0; ks < 4; ks++) {
            uint32_t ph[4], pl[4];
            split2(s[2 * ks][0], s[2 * ks][1], ph[0], pl[0]);
            split2(s[2 * ks][2], s[2 * ks][3], ph[1], pl[1]);
            split2(s[2 * ks + 1][0], s[2 * ks + 1][1], ph[2], pl[2]);
            split2(s[2 * ks + 1][2], s[2 * ks + 1][3], ph[3], pl[3]);
#pragma unroll
            for (int nt = 0; nt < 8; nt++) {
                uint32_t vh[2], vl[2];
                const uint32_t ad = smb + A_VH + (ks * 16 + (lane & 15)) * AROW + nt * 16;
                ldmx2t(vh, ad);
                ldmx2t(vl, ad + (A_VL - A_VH));
                mma_bf16(accO[nt], ph, vh);
                mma_bf16(accO[nt], ph, vl);
                mma_bf16(accO[nt], pl, vh);
            }
        }
    }

    // Epilogue: normalize, split hi/lo, write merged [B,L,H]
    const int b = bh / NH_, hh = bh % NH_;
#pragma unroll
    for (int h = 0; h < 2; h++) {
        const float inv = 1.0f / lrow[h];
        const int q = qt * AQ + w * 16 + lr + h * 8;
        const size_t base = ((size_t)b * L_ + q) * H_ + hh * HD_;
#pragma unroll
        for (int nt = 0; nt < 8; nt++) {
            const float v0 = accO[nt][h * 2 + 0] * inv;
            const float v1 = accO[nt][h * 2 + 1] * inv;
            uint32_t ph, pl;
            split2(v0, v1, ph, pl);
            *(uint32_t*)(g_aoh + base + nt * 8 + lc) = ph;
            *(uint32_t*)(g_aol + base + nt * 8 + lc) = pl;
        }
    }
}

// ---------------------------------------------------------------------------
// Launch
// ---------------------------------------------------------------------------
extern "C" void kernel_launch(void* const* d_in, const int* in_sizes, int n_in,
                              void* d_out, int out_size) {
    const float* q    = (const float*)d_in[0];
    const float* k    = (const float*)d_in[1];
    const float* v    = (const float*)d_in[2];
    const float* mask = (const float*)d_in[3];
    const float* Wq   = (const float*)d_in[4];
    const float* bq   = (const float*)d_in[5];
    const float* Wk   = (const float*)d_in[6];
    const float* bk   = (const float*)d_in[7];
    const float* Wv   = (const float*)d_in[8];
    const float* bv   = (const float*)d_in[9];
    const float* Wo   = (const float*)d_in[10];
    const float* bo   = (const float*)d_in[11];
    float* out = (float*)d_out;

    cudaFuncSetAttribute(gemm_qkv_tc, cudaFuncAttributeMaxDynamicSharedMemorySize, GSMEM);
    cudaFuncSetAttribute(gemm_out_tc, cudaFuncAttributeMaxDynamicSharedMemorySize, GSMEM);
    cudaFuncSetAttribute(attn_mma, cudaFuncAttributeMaxDynamicSharedMemorySize, ASMEM);

    // 1) split q,k,v inputs -> bf16 hi/lo
    split3_kernel<<<dim3(NM_ / 1024, 3), 256>>>(q, k, v);
    // 2) transpose+split all 4 weights
    wsplit_t_kernel<<<dim3(32, 32, 4), 256>>>(Wq, Wk, Wv, Wo);
    // 3) Q/K/V projections (tensor cores; head-split fp32 + bf16 hi/lo outputs)
    gemm_qkv_tc<<<dim3(H_ / GBN, M_ / GBM, 3), 256, GSMEM>>>(bq, bk, bv);
    // 4) attention on tensor cores (bf16 split, fp32 softmax)
    attn_mma<<<dim3(L_ / AQ, B_ * NH_), 256, ASMEM>>>(mask);
    // 5) output projection (tensor cores)
    gemm_out_tc<<<dim3(H_ / GBN, M_ / GBM), 256, GSMEM>>>(bo, out);
}